// round 17
// baseline (speedup 1.0000x reference)
#include <cuda_runtime.h>
#include <cuda_fp16.h>

#define BT 16
#define HH 48
#define WW 48
#define NPIX (BT*HH*WW)   /* 36864 */
#define QSCALE 0.35355339059327373f

// Scratch (static device allocations are allowed)
__device__ float g_Q[NPIX*64];
__device__ float g_K[NPIX*64];
__device__ float g_V[NPIX*64];

extern __shared__ float sdyn[];

// ---------------------------------------------------------------------------
// FMA-only exp (no MUFU), rel err ~2.4e-6
// ---------------------------------------------------------------------------
__device__ __forceinline__ float fexp(float x) {
    float z  = fmaf(x, 1.4426950408889634f, 12582912.0f);
    int   iz = __float_as_int(z);
    float n  = z - 12582912.0f;
    float f  = fmaf(n, -0.6931471805599453f, x);
    float p  = 8.3333333e-3f;
    p = fmaf(p, f, 4.1666667e-2f);
    p = fmaf(p, f, 1.6666667e-1f);
    p = fmaf(p, f, 5.0e-1f);
    p = fmaf(p, f, 1.0f);
    p = fmaf(p, f, 1.0f);
    return __int_as_float(__float_as_int(p) + (iz << 23));
}

// ---------------------------------------------------------------------------
// Kernel 1: QKV projection, register-tiled SGEMM.
// Thread mapping: cx = tid>>4 (col group), ry = tid&15 (row group) ->
// half-warp constant cx (wT broadcast) + ry-contiguous xT (conflict-free).
// ---------------------------------------------------------------------------
#define XPAD 132
#define WPAD 100
#define QKV_SMEM ((64*XPAD + 64*WPAD)*4)

__global__ __launch_bounds__(192) void qkv_kernel(const float* __restrict__ x,
                                                  const float* __restrict__ w,
                                                  const float* __restrict__ b) {
    float* xT = sdyn;              // [ch_slot][row 128]
    float* wT = sdyn + 64*XPAD;    // [ch_slot][col 96]
    int tid = threadIdx.x;
    int row0 = blockIdx.x * 128;
    int chunk = blockIdx.y * 96;

    const float4* x4 = (const float4*)(x + (size_t)row0*64);
    for (int idx = tid; idx < 128*16; idx += 192) {
        int r = idx >> 4, cq = idx & 15;
        float4 v = x4[idx];
        float vv[4] = {v.x, v.y, v.z, v.w};
        #pragma unroll
        for (int k = 0; k < 4; k++) {
            int s = cq*4 + ((k + cq) & 3);
            xT[s*XPAD + r] = vv[k];
        }
    }
    const float4* w4 = (const float4*)(w + (size_t)chunk*64);
    for (int idx = tid; idx < 96*16; idx += 192) {
        int o = idx >> 4, cq = idx & 15;
        float4 v = w4[idx];
        float vv[4] = {v.x, v.y, v.z, v.w};
        #pragma unroll
        for (int k = 0; k < 4; k++) {
            int s = cq*4 + ((k + cq) & 3);
            wT[s*WPAD + o] = vv[k];
        }
    }
    __syncthreads();

    int cx = tid >> 4, ry = tid & 15;     // 12 col-groups x 16 row-groups
    int r0 = ry*8, c0 = cx*8;

    float acc[8][8];
    #pragma unroll
    for (int i = 0; i < 8; i++)
        #pragma unroll
        for (int j = 0; j < 8; j++) acc[i][j] = 0.f;

    #pragma unroll 4
    for (int s = 0; s < 64; s++) {
        float4 xa = *(const float4*)&xT[s*XPAD + r0];
        float4 xb = *(const float4*)&xT[s*XPAD + r0 + 4];
        float4 wa = *(const float4*)&wT[s*WPAD + c0];
        float4 wb = *(const float4*)&wT[s*WPAD + c0 + 4];
        float xr[8] = {xa.x,xa.y,xa.z,xa.w, xb.x,xb.y,xb.z,xb.w};
        float wc[8] = {wa.x,wa.y,wa.z,wa.w, wb.x,wb.y,wb.z,wb.w};
        #pragma unroll
        for (int i = 0; i < 8; i++)
            #pragma unroll
            for (int j = 0; j < 8; j++)
                acc[i][j] = fmaf(xr[i], wc[j], acc[i][j]);
    }

    int oc = chunk + c0;
    float bias[8];
    *(float4*)&bias[0] = __ldg((const float4*)(b + oc));
    *(float4*)&bias[4] = __ldg((const float4*)(b + oc + 4));
    float scale = (oc < 64) ? QSCALE : 1.f;
    float* dstbase = (oc < 64) ? g_Q : (oc < 128 ? g_K : g_V);
    int cc0 = oc & 63;
    #pragma unroll
    for (int i = 0; i < 8; i++) {
        size_t rb = (size_t)(row0 + r0 + i)*64 + cc0;
        float4 o0, o1;
        o0.x = (acc[i][0]+bias[0])*scale; o0.y = (acc[i][1]+bias[1])*scale;
        o0.z = (acc[i][2]+bias[2])*scale; o0.w = (acc[i][3]+bias[3])*scale;
        o1.x = (acc[i][4]+bias[4])*scale; o1.y = (acc[i][5]+bias[5])*scale;
        o1.z = (acc[i][6]+bias[6])*scale; o1.w = (acc[i][7]+bias[7])*scale;
        *(float4*)&dstbase[rb]     = o0;
        *(float4*)&dstbase[rb + 4] = o1;
    }
}

// ---------------------------------------------------------------------------
// Kernel 2: attention (fp16 K/V smem; full-dot + full-V query ownership;
// zero shuffles in the hot loop) + proj + LN.
// Block = 768 threads = (j, head, half f). Thread owns query row i0+f:
// 8-ch HFMA2 dot (K LDS.128), 1 fexp, 8-ch V accumulation (V LDS.128,
// broadcast across the f-pair). smem ~99KB -> 2 blocks/SM.
// ---------------------------------------------------------------------------
#define KV_H2   (8*48*32)            /* half2 per array: 12288 (=49152 B) */
#define RPB_OFFB (2*KV_H2*4)         /* byte offset of rpb: 98304 */
#define ATTN_SMEM (RPB_OFFB + 8*169*4 + 256)

__global__ __launch_bounds__(768, 2) void attn_proj_kernel(const float* __restrict__ rpb,
                                                        const float* __restrict__ pw,
                                                        const float* __restrict__ pb,
                                                        const float* __restrict__ lng,
                                                        const float* __restrict__ lnb,
                                                        float* __restrict__ out) {
    __half2* Ksh  = (__half2*)sdyn;              // [r][pix][h*4 half2] head-contig
    __half2* Vsh  = (__half2*)sdyn + KV_H2;      // [r][pix][h*4 half2] head-contig
    float* rpb_s  = (float*)((char*)sdyn + RPB_OFFB);
    float* xout   = sdyn;                    // alias over K region: [96][64] f32
    float* pws    = sdyn + 12288;            // alias over V region: [64][68] f32

    int tid = threadIdx.x;
    int blk = blockIdx.x;
    int bt = blk / 24, i0 = (blk % 24) * 2;
    int strip = bt * 2304;

    for (int idx = tid; idx < 8*169; idx += 768) rpb_s[idx] = rpb[idx];

    // ---- stage K/V as fp16, head-contiguous (8B stores, conflict-free)
    int r0 = min(max(i0 - 3, 0), 41);
    {
        const float4* Kg4 = (const float4*)g_K;
        const float4* Vg4 = (const float4*)g_V;
        int c = tid >> 4, s = tid & 15;
        int dst = c*32 + s*2;
        int srcb = (strip + c)*16 + s;
        #pragma unroll
        for (int r = 0; r < 8; r++) {
            int gi = min(r0 + r, 47);
            int src = srcb + gi*768;
            float4 kv = Kg4[src];
            float4 vv = Vg4[src];
            __half2 k0 = __floats2half2_rn(kv.x, kv.y);
            __half2 k1 = __floats2half2_rn(kv.z, kv.w);
            __half2 v0 = __floats2half2_rn(vv.x, vv.y);
            __half2 v1 = __floats2half2_rn(vv.z, vv.w);
            *(uint2*)(Ksh + r*1536 + dst) = make_uint2(*(unsigned*)&k0, *(unsigned*)&k1);
            *(uint2*)(Vsh + r*1536 + dst) = make_uint2(*(unsigned*)&v0, *(unsigned*)&v1);
        }
    }
    __syncthreads();

    // ---- attention
    int j = tid >> 4;
    int f = (tid >> 3) & 1;
    int h = tid & 7;
    int sj  = min(max(j - 3, 0), 41);

    int iqM = i0 + f;                          // my query row
    int dM  = min(max(iqM - 3, 0), 41) - r0;   // 0 or 1

    // my query, all 8 channels, as 4x half2
    const float4* Q4 = (const float4*)g_Q;
    float4 qa = Q4[(strip + iqM*48 + j)*16 + h*2];
    float4 qb = Q4[(strip + iqM*48 + j)*16 + h*2 + 1];
    __half2 qh0 = __floats2half2_rn(qa.x, qa.y);
    __half2 qh1 = __floats2half2_rn(qa.z, qa.w);
    __half2 qh2 = __floats2half2_rn(qb.x, qb.y);
    __half2 qh3 = __floats2half2_rn(qb.z, qb.w);

    float o0=0,o1=0,o2=0,o3=0,o4=0,o5=0,o6=0,o7=0;
    float lM = 0.f;

    const float* hb = rpb_s + h*169;
    int bcol = sj - j + 6;
    int briM = r0 - iqM + 6;
    int kofs = h*4;                    // half2 offset of my head's 8 channels

    #pragma unroll 2
    for (int r = 0; r < 8; r++) {
        float wM = ((unsigned)(r - dM) < 7u) ? 1.f : 0.f;
        const float* bM = hb + (briM + r)*13 + bcol;
        const __half2* kp = Ksh + r*1536 + sj*32 + kofs;
        const __half2* vp = Vsh + r*1536 + sj*32 + kofs;
        #pragma unroll
        for (int c = 0; c < 7; c++) {
            uint4 kr = *(const uint4*)(kp + c*32);
            uint4 vr = *(const uint4*)(vp + c*32);
            __half2 p0 = __hmul2(qh0, *(__half2*)&kr.x);
            __half2 p1 = __hmul2(qh1, *(__half2*)&kr.y);
            p0 = __hfma2(qh2, *(__half2*)&kr.z, p0);
            p1 = __hfma2(qh3, *(__half2*)&kr.w, p1);
            p0 = __hadd2(p0, p1);
            float2 pf = __half22float2(p0);
            float e = fexp(pf.x + pf.y + bM[c]) * wM;
            lM += e;
            float2 v0 = __half22float2(*(__half2*)&vr.x);
            float2 v1 = __half22float2(*(__half2*)&vr.y);
            float2 v2 = __half22float2(*(__half2*)&vr.z);
            float2 v3 = __half22float2(*(__half2*)&vr.w);
            o0 = fmaf(e, v0.x, o0); o1 = fmaf(e, v0.y, o1);
            o2 = fmaf(e, v1.x, o2); o3 = fmaf(e, v1.y, o3);
            o4 = fmaf(e, v2.x, o4); o5 = fmaf(e, v2.y, o5);
            o6 = fmaf(e, v3.x, o6); o7 = fmaf(e, v3.y, o7);
        }
    }
    __syncthreads();   // all Ksh/Vsh reads done; safe to alias

    // ---- write attention outputs to xout [96][64]
    {
        float inv = 1.f / lM;
        float4 u0 = make_float4(o0*inv, o1*inv, o2*inv, o3*inv);
        float4 u1 = make_float4(o4*inv, o5*inv, o6*inv, o7*inv);
        *(float4*)(xout + (f*48 + j)*64 + h*8)     = u0;
        *(float4*)(xout + (f*48 + j)*64 + h*8 + 4) = u1;
    }
    // ---- stage proj weights [64][68]
    {
        const float4* pw4 = (const float4*)pw;
        for (int idx = tid; idx < 1024; idx += 768) {
            int cch = idx >> 4, qq = idx & 15;
            *(float4*)(pws + cch*68 + qq*4) = pw4[idx];
        }
    }
    __syncthreads();

    // ---- proj + LayerNorm: warp = 4 rows; lane = channels {lane, lane+32}
    int warp = tid >> 5, lane = tid & 31;
    int c0 = lane, c1 = lane + 32;
    const float4* w0p = (const float4*)(pws + c0*68);
    const float4* w1p = (const float4*)(pws + c1*68);
    float pb0 = __ldg(&pb[c0]),  pb1 = __ldg(&pb[c1]);
    float g0  = __ldg(&lng[c0]), g1  = __ldg(&lng[c1]);
    float bb0 = __ldg(&lnb[c0]), bb1 = __ldg(&lnb[c1]);
    int row0l = warp * 4;

    float y[4][2];
    #pragma unroll
    for (int rr = 0; rr < 4; rr++) { y[rr][0] = 0.f; y[rr][1] = 0.f; }

    #pragma unroll
    for (int cc = 0; cc < 16; cc++) {
        float4 wv0 = w0p[cc];
        float4 wv1 = w1p[cc];
        #pragma unroll
        for (int rr = 0; rr < 4; rr++) {
            float4 xv = *(const float4*)(xout + (row0l + rr)*64 + cc*4);
            y[rr][0] += xv.x*wv0.x + xv.y*wv0.y + xv.z*wv0.z + xv.w*wv0.w;
            y[rr][1] += xv.x*wv1.x + xv.y*wv1.y + xv.z*wv1.z + xv.w*wv1.w;
        }
    }

    #pragma unroll
    for (int rr = 0; rr < 4; rr++) {
        float y0 = y[rr][0] + pb0;
        float y1 = y[rr][1] + pb1;
        float s  = y0 + y1;
        float sq = y0*y0 + y1*y1;
        #pragma unroll
        for (int off = 16; off; off >>= 1) {
            s  += __shfl_xor_sync(0xffffffffu, s,  off);
            sq += __shfl_xor_sync(0xffffffffu, sq, off);
        }
        float mu  = s * (1.f/64.f);
        float var = sq * (1.f/64.f) - mu*mu;
        float rs  = rsqrtf(var + 1e-5f);

        int lr = row0l + rr;
        int irow = (lr >= 48);
        int pix = strip + (i0 + irow)*48 + (lr - irow*48);
        out[(size_t)pix*64 + c0] = (y0 - mu)*rs*g0 + bb0;
        out[(size_t)pix*64 + c1] = (y1 - mu)*rs*g1 + bb1;
    }
}

// ---------------------------------------------------------------------------
extern "C" void kernel_launch(void* const* d_in, const int* in_sizes, int n_in,
                              void* d_out, int out_size) {
    const float* q      = (const float*)d_in[0];
    const float* qkv_w  = (const float*)d_in[1];
    const float* qkv_b  = (const float*)d_in[2];
    const float* proj_w = (const float*)d_in[3];
    const float* proj_b = (const float*)d_in[4];
    const float* rpb    = (const float*)d_in[5];
    const float* ln_g   = (const float*)d_in[6];
    const float* ln_b   = (const float*)d_in[7];

    cudaFuncSetAttribute(qkv_kernel,
                         cudaFuncAttributeMaxDynamicSharedMemorySize, QKV_SMEM);
    cudaFuncSetAttribute(attn_proj_kernel,
                         cudaFuncAttributeMaxDynamicSharedMemorySize, ATTN_SMEM);

    qkv_kernel<<<dim3(NPIX/128, 2), 192, QKV_SMEM>>>(q, qkv_w, qkv_b);
    attn_proj_kernel<<<384, 768, ATTN_SMEM>>>(rpb, proj_w, proj_b,
                                              ln_g, ln_b, (float*)d_out);
}